// round 3
// baseline (speedup 1.0000x reference)
#include <cuda_runtime.h>
#include <cstdint>

#define NIMG 64
#define CDIM 256
#define HWD 28
#define PIXPERIMG 784
#define NPIX 50176   /* 64*784 */
#define PDIM 256
#define EPSV 1e-5f

// ---------------- scratch (device globals; no allocation allowed) ----------------
__device__ int8_t g_xb1[NPIX * CDIM];          // sign(bn1(x)) NHWC int8
__device__ int8_t g_xb2[NPIX * PDIM];          // sign(bn2(relu(y1*s1))) NHWC int8
__device__ int8_t g_wbt1[9 * PDIM * CDIM];     // [tap][p][c]
__device__ int8_t g_wbt2[9 * PDIM * PDIM];
__device__ short  g_y1[NPIX * PDIM];           // raw conv1 int result NHWC
__device__ short  g_y2[NPIX * PDIM];           // raw conv2 int result NHWC
__device__ float  g_red[1536];                 // [0:512) bn1 sums, [512:1024) bn2, [1024:1536) bn3
__device__ float  g_A1[CDIM], g_T1[CDIM];      // bn1 sign-threshold coeffs
__device__ float  g_A2[PDIM], g_T2[PDIM];      // bn2 sign-threshold coeffs
__device__ float  g_sc3[PDIM], g_sh3[PDIM];    // bn3 affine

// ---------------- tiny init ----------------
__global__ void zero_kernel() {
    for (int i = threadIdx.x; i < 1536; i += blockDim.x) g_red[i] = 0.f;
}

// ---------------- bn1 stats over x (NCHW): one CTA per channel ----------------
__global__ void reduce_x_kernel(const float* __restrict__ x) {
    int c = blockIdx.x;
    int tid = threadIdx.x;
    float s = 0.f, s2 = 0.f;
    const float* xc = x + (size_t)c * PIXPERIMG;
    for (int n = 0; n < NIMG; n++) {
        const float* p = xc + (size_t)n * (CDIM * PIXPERIMG);
        for (int i = tid; i < PIXPERIMG; i += 256) {
            float v = p[i];
            s += v; s2 += v * v;
        }
    }
    __shared__ float sh[256], sh2[256];
    sh[tid] = s; sh2[tid] = s2;
    __syncthreads();
    for (int o = 128; o > 0; o >>= 1) {
        if (tid < o) { sh[tid] += sh[tid + o]; sh2[tid] += sh2[tid + o]; }
        __syncthreads();
    }
    if (tid == 0) { g_red[c] = sh[0]; g_red[256 + c] = sh2[0]; }
}

// ---------------- binarize weights: sign(w - mean over input channels) ----------
// grid (256 p, 2 layer), 256 threads (c)
__global__ void binw_kernel(const float* __restrict__ w1, const float* __restrict__ w2) {
    int p = blockIdx.x;
    int layer = blockIdx.y;
    const float* w = layer ? w2 : w1;
    int8_t* o = layer ? g_wbt2 : g_wbt1;
    int c = threadIdx.x;
    __shared__ float sh[256];
    const float* wp = w + ((size_t)p * 256 + c) * 9;
    float wv[9];
#pragma unroll
    for (int t = 0; t < 9; t++) wv[t] = wp[t];
    for (int t = 0; t < 9; t++) {
        sh[c] = wv[t];
        __syncthreads();
        for (int ofs = 128; ofs > 0; ofs >>= 1) {
            if (c < ofs) sh[c] += sh[c + ofs];
            __syncthreads();
        }
        float mean = sh[0] * (1.f / 256.f);
        __syncthreads();
        o[t * 65536 + p * 256 + c] = (wv[t] > mean) ? (int8_t)1 : (int8_t)-1;
    }
}

// ---------------- threshold coeffs for sign(bn(.)) ----------------
__global__ void make_thresh_kernel(int which, const float* __restrict__ g, const float* __restrict__ b) {
    int c = threadIdx.x;
    const float* red = which ? (g_red + 512) : g_red;
    float* A = which ? g_A2 : g_A1;
    float* T = which ? g_T2 : g_T1;
    float m = red[c] * (1.f / (float)NPIX);
    float var = red[256 + c] * (1.f / (float)NPIX) - m * m;
    A[c] = g[c];
    T[c] = b[c] * sqrtf(var + EPSV) - g[c] * m;
}

__global__ void make_bn3_kernel(const float* __restrict__ g, const float* __restrict__ b) {
    int c = threadIdx.x;
    float m = g_red[1024 + c] * (1.f / (float)NPIX);
    float var = g_red[1024 + 256 + c] * (1.f / (float)NPIX) - m * m;
    float sc = g[c] * rsqrtf(var + EPSV);
    g_sc3[c] = sc;
    g_sh3[c] = b[c] - m * sc;
}

// ---------------- binarize x: NCHW fp32 -> NHWC int8 via smem transpose ---------
// grid (7 pixblk, 8 cblk, 64 n), 256 threads. tile = 112 pixels x 32 channels.
__global__ void binx_kernel(const float* __restrict__ x) {
    __shared__ __align__(16) int8_t s[112 * 48];
    int tid = threadIdx.x;
    int pb = blockIdx.x * 112;
    int cb = blockIdx.y * 32;
    int n  = blockIdx.z;
#pragma unroll
    for (int i = 0; i < 14; i++) {
        int e = tid + i * 256;
        int cl = e / 112, pix = e % 112;
        int c = cb + cl;
        float v = x[((size_t)(n * CDIM + c)) * PIXPERIMG + pb + pix];
        s[pix * 48 + cl] = (g_A1[c] * v + g_T1[c] >= 0.f) ? (int8_t)1 : (int8_t)-1;
    }
    __syncthreads();
    if (tid < 224) {
        int pix = tid >> 1, half = tid & 1;
        uint4 v = *(const uint4*)&s[pix * 48 + half * 16];
        *(uint4*)(g_xb1 + (((size_t)(n * PIXPERIMG + pb + pix)) << 8) + cb + half * 16) = v;
    }
}

// ---------------- binarize y1 -> xb2 (both NHWC, fully coalesced) ----------------
__global__ void biny_kernel(const float* __restrict__ gamma1,
                            const float* __restrict__ alpha1,
                            const float* __restrict__ beta1) {
    int idx = blockIdx.x * 256 + threadIdx.x;
    int base = idx << 2;                 // 4 consecutive channels, same pixel
    int pix = base >> 8;
    int c0 = base & 255;
    int r = pix % PIXPERIMG;
    float ab = alpha1[r / HWD] * beta1[r % HWD];
    short4 v = *reinterpret_cast<const short4*>(g_y1 + base);
    int cv[4] = {v.x, v.y, v.z, v.w};
    uint32_t o = 0;
#pragma unroll
    for (int j = 0; j < 4; j++) {
        int c = c0 + j;
        float val = (float)cv[j] * (gamma1[c] * ab);
        float rr = fmaxf(val, 0.f);
        int8_t sg = (g_A2[c] * rr + g_T2[c] >= 0.f) ? (int8_t)1 : (int8_t)-1;
        o |= ((uint32_t)(uint8_t)sg) << (8 * j);
    }
    *reinterpret_cast<uint32_t*>(g_xb2 + base) = o;
}

// ---------------- implicit-GEMM binary conv via int8 mma.sync -------------------
// M = 50176 pixels, N = 256 out channels, K = 9 taps * 256 in channels.
// CTA tile 128x128, K-chunk 64 (2 x m16n8k32 per fragment set).
// Epilogue: store raw int16 NHWC + fused per-channel (sum, sumsq) of scaled
// (optionally ReLU'd) values for the NEXT BatchNorm's batch statistics.
__global__ void __launch_bounds__(256, 2)
conv_kernel(int layer, const float* __restrict__ gamma,
            const float* __restrict__ alpha, const float* __restrict__ beta) {
    const int8_t* Ag = layer ? g_xb2 : g_xb1;
    const int8_t* Wg = layer ? g_wbt2 : g_wbt1;
    short* Yg = layer ? g_y2 : g_y1;
    float* red = g_red + (layer ? 1024 : 512);
    const bool doRelu = (layer == 0);

    __shared__ __align__(16) int8_t Abuf[2][128 * 80];
    __shared__ __align__(16) int8_t Bbuf[2][128 * 80];
    __shared__ int pixbytes[128];
    __shared__ signed char pyv[128], pxv[128];

    int tid = threadIdx.x;
    int mbase = blockIdx.x * 128;
    int pbase = blockIdx.y * 128;

    if (tid < 128) {
        int pix = mbase + tid;
        int r = pix % PIXPERIMG;
        pixbytes[tid] = pix << 8;
        pyv[tid] = (signed char)(r / HWD);
        pxv[tid] = (signed char)(r % HWD);
    }
    __syncthreads();

    auto stage = [&](int chunk, int buf) {
        int t = chunk >> 2, cb = chunk & 3;
        int dy = t / 3 - 1, dx = t % 3 - 1;
        int tapoff = (dy * HWD + dx) << 8;
        int cofs = cb * 64;
#pragma unroll
        for (int i = 0; i < 2; i++) {
            int id = tid + i * 256;
            int row = id >> 2, seg = id & 3;
            int yy = (int)pyv[row] + dy, xx = (int)pxv[row] + dx;
            bool valid = ((unsigned)yy < (unsigned)HWD) && ((unsigned)xx < (unsigned)HWD);
            const int8_t* gp = Ag + pixbytes[row] + tapoff + cofs + seg * 16;
            uint32_t sa = (uint32_t)__cvta_generic_to_shared(&Abuf[buf][row * 80 + seg * 16]);
            int sz = valid ? 16 : 0;
            asm volatile("cp.async.cg.shared.global [%0], [%1], 16, %2;\n"
                         :: "r"(sa), "l"(gp), "r"(sz));
        }
#pragma unroll
        for (int i = 0; i < 2; i++) {
            int id = tid + i * 256;
            int row = id >> 2, seg = id & 3;
            const int8_t* gp = Wg + t * 65536 + (pbase + row) * 256 + cofs + seg * 16;
            uint32_t sa = (uint32_t)__cvta_generic_to_shared(&Bbuf[buf][row * 80 + seg * 16]);
            asm volatile("cp.async.cg.shared.global [%0], [%1], 16, 16;\n"
                         :: "r"(sa), "l"(gp));
        }
        asm volatile("cp.async.commit_group;\n");
    };

    int wid = tid >> 5, lane = tid & 31;
    int warpM = wid & 1, warpN = wid >> 1;     // 2 x 4 warp grid; warp tile 64x32
    int gid = lane >> 2, tig = lane & 3;

    int acc[4][4][4];
#pragma unroll
    for (int a = 0; a < 4; a++)
#pragma unroll
        for (int b = 0; b < 4; b++)
#pragma unroll
            for (int c = 0; c < 4; c++) acc[a][b][c] = 0;

    stage(0, 0);

    for (int k = 0; k < 36; k++) {
        if (k + 1 < 36) {
            stage(k + 1, (k + 1) & 1);
            asm volatile("cp.async.wait_group 1;\n");
        } else {
            asm volatile("cp.async.wait_group 0;\n");
        }
        __syncthreads();
        const int8_t* As = Abuf[k & 1];
        const int8_t* Bs = Bbuf[k & 1];
#pragma unroll
        for (int h = 0; h < 2; h++) {
            uint32_t af[4][4];
#pragma unroll
            for (int mi = 0; mi < 4; mi++) {
                int rb = (warpM * 64 + mi * 16 + gid) * 80 + h * 32 + tig * 4;
                af[mi][0] = *(const uint32_t*)(As + rb);
                af[mi][1] = *(const uint32_t*)(As + rb + 8 * 80);
                af[mi][2] = *(const uint32_t*)(As + rb + 16);
                af[mi][3] = *(const uint32_t*)(As + rb + 8 * 80 + 16);
            }
            uint32_t bf[4][2];
#pragma unroll
            for (int ni = 0; ni < 4; ni++) {
                int rb = (warpN * 32 + ni * 8 + gid) * 80 + h * 32 + tig * 4;
                bf[ni][0] = *(const uint32_t*)(Bs + rb);
                bf[ni][1] = *(const uint32_t*)(Bs + rb + 16);
            }
#pragma unroll
            for (int mi = 0; mi < 4; mi++)
#pragma unroll
                for (int ni = 0; ni < 4; ni++) {
                    asm volatile(
                        "mma.sync.aligned.m16n8k32.row.col.s32.s8.s8.s32 "
                        "{%0,%1,%2,%3}, {%4,%5,%6,%7}, {%8,%9}, {%0,%1,%2,%3};\n"
                        : "+r"(acc[mi][ni][0]), "+r"(acc[mi][ni][1]),
                          "+r"(acc[mi][ni][2]), "+r"(acc[mi][ni][3])
                        : "r"(af[mi][0]), "r"(af[mi][1]), "r"(af[mi][2]), "r"(af[mi][3]),
                          "r"(bf[ni][0]), "r"(bf[ni][1]));
                }
        }
        __syncthreads();
    }

    // ---- epilogue: int16 store + fused per-channel stats of scaled values ----
    float gm[4][2];
#pragma unroll
    for (int ni = 0; ni < 4; ni++) {
        gm[ni][0] = gamma[pbase + warpN * 32 + ni * 8 + tig * 2 + 0];
        gm[ni][1] = gamma[pbase + warpN * 32 + ni * 8 + tig * 2 + 1];
    }
    float sv[4][2], sq[4][2];
#pragma unroll
    for (int ni = 0; ni < 4; ni++) { sv[ni][0] = sv[ni][1] = sq[ni][0] = sq[ni][1] = 0.f; }

#pragma unroll
    for (int mi = 0; mi < 4; mi++) {
#pragma unroll
        for (int rh = 0; rh < 2; rh++) {
            int prow = warpM * 64 + mi * 16 + rh * 8 + gid;
            int pix = mbase + prow;
            float ab = alpha[(int)pyv[prow]] * beta[(int)pxv[prow]];
#pragma unroll
            for (int ni = 0; ni < 4; ni++) {
                int i0 = acc[mi][ni][rh * 2 + 0];
                int i1 = acc[mi][ni][rh * 2 + 1];
                float v0 = (float)i0 * (gm[ni][0] * ab);
                float v1 = (float)i1 * (gm[ni][1] * ab);
                if (doRelu) { v0 = fmaxf(v0, 0.f); v1 = fmaxf(v1, 0.f); }
                sv[ni][0] += v0; sq[ni][0] += v0 * v0;
                sv[ni][1] += v1; sq[ni][1] += v1 * v1;
                uint32_t packed = (uint32_t)(uint16_t)(short)i0 |
                                  ((uint32_t)(uint16_t)(short)i1 << 16);
                *(uint32_t*)(Yg + (size_t)pix * 256 + pbase + warpN * 32 + ni * 8 + tig * 2) = packed;
            }
        }
    }
    // reduce over the 8 groupID lanes (lane bits 2..4)
#pragma unroll
    for (int ofs = 4; ofs <= 16; ofs <<= 1) {
#pragma unroll
        for (int ni = 0; ni < 4; ni++) {
#pragma unroll
            for (int c = 0; c < 2; c++) {
                sv[ni][c] += __shfl_xor_sync(0xffffffff, sv[ni][c], ofs);
                sq[ni][c] += __shfl_xor_sync(0xffffffff, sq[ni][c], ofs);
            }
        }
    }
    if (gid == 0) {
#pragma unroll
        for (int ni = 0; ni < 4; ni++) {
#pragma unroll
            for (int c = 0; c < 2; c++) {
                int p = pbase + warpN * 32 + ni * 8 + tig * 2 + c;
                atomicAdd(&red[p], sv[ni][c]);
                atomicAdd(&red[256 + p], sq[ni][c]);
            }
        }
    }
}

// ---------------- final: out = relu(bn3(y2*s2) + x), NHWC int16 -> NCHW fp32 ----
__global__ void final_kernel(const float* __restrict__ x,
                             const float* __restrict__ gamma2,
                             const float* __restrict__ alpha2,
                             const float* __restrict__ beta2,
                             float* __restrict__ out) {
    __shared__ float fs[32 * 113];
    int tid = threadIdx.x;
    int pb = blockIdx.x * 112;
    int cb = blockIdx.y * 32;
    int n  = blockIdx.z;
#pragma unroll
    for (int i = 0; i < 14; i++) {
        int e = tid + i * 256;
        int pix = e >> 5, cl = e & 31;
        int c = cb + cl;
        int pg = pb + pix;                     // pixel within image
        int cint = g_y2[(((size_t)(n * PIXPERIMG + pg)) << 8) + c];
        float v = (float)cint * (gamma2[c] * alpha2[pg / HWD] * beta2[pg % HWD]);
        fs[cl * 113 + pix] = v * g_sc3[c] + g_sh3[c];
    }
    __syncthreads();
#pragma unroll
    for (int i = 0; i < 14; i++) {
        int e = tid + i * 256;
        int cl = e / 112, pix = e % 112;
        int c = cb + cl;
        size_t gi = ((size_t)(n * CDIM + c)) * PIXPERIMG + pb + pix;
        out[gi] = fmaxf(fs[cl * 113 + pix] + x[gi], 0.f);
    }
}

// ---------------- launch ----------------
extern "C" void kernel_launch(void* const* d_in, const int* in_sizes, int n_in,
                              void* d_out, int out_size) {
    (void)in_sizes; (void)n_in; (void)out_size;
    const float* x      = (const float*)d_in[0];
    const float* bn1_g  = (const float*)d_in[1];
    const float* bn1_b  = (const float*)d_in[2];
    const float* bn2_g  = (const float*)d_in[3];
    const float* bn2_b  = (const float*)d_in[4];
    const float* bn3_g  = (const float*)d_in[5];
    const float* bn3_b  = (const float*)d_in[6];
    const float* w1     = (const float*)d_in[7];
    const float* gamma1 = (const float*)d_in[8];
    const float* alpha1 = (const float*)d_in[9];
    const float* beta1  = (const float*)d_in[10];
    const float* w2     = (const float*)d_in[11];
    const float* gamma2 = (const float*)d_in[12];
    const float* alpha2 = (const float*)d_in[13];
    const float* beta2  = (const float*)d_in[14];
    float* out = (float*)d_out;

    zero_kernel<<<1, 512>>>();
    reduce_x_kernel<<<256, 256>>>(x);
    binw_kernel<<<dim3(256, 2), 256>>>(w1, w2);
    make_thresh_kernel<<<1, 256>>>(0, bn1_g, bn1_b);
    binx_kernel<<<dim3(7, 8, 64), 256>>>(x);
    conv_kernel<<<dim3(392, 2), 256>>>(0, gamma1, alpha1, beta1);
    make_thresh_kernel<<<1, 256>>>(1, bn2_g, bn2_b);
    biny_kernel<<<12544, 256>>>(gamma1, alpha1, beta1);
    conv_kernel<<<dim3(392, 2), 256>>>(1, gamma2, alpha2, beta2);
    make_bn3_kernel<<<1, 256>>>(bn3_g, bn3_b);
    final_kernel<<<dim3(7, 8, 64), 256>>>(x, gamma2, alpha2, beta2, out);
}

// round 6
// speedup vs baseline: 1.1854x; 1.1854x over previous
#include <cuda_runtime.h>
#include <cstdint>

#define NIMG 64
#define CDIM 256
#define HWD 28
#define PIXPERIMG 784
#define NPIX 50176   /* 64*784 */
#define PDIM 256
#define EPSV 1e-5f

// ---------------- scratch (device globals; no allocation allowed) ----------------
__device__ int8_t g_xb1[NPIX * CDIM];          // sign(bn1(x)) NHWC int8
__device__ int8_t g_xb2[NPIX * PDIM];          // sign(bn2(relu(y1*s1))) NHWC int8
__device__ int8_t g_wbt1[9 * PDIM * CDIM];     // [tap][p][c]
__device__ int8_t g_wbt2[9 * PDIM * PDIM];
__device__ short  g_y1[NPIX * PDIM];           // raw conv1 int result NHWC
__device__ short  g_y2[NPIX * PDIM];           // raw conv2 int result NHWC
__device__ float  g_red[1536];                 // [0:512) bn1, [512:1024) bn2, [1024:1536) bn3
__device__ float  g_A1[CDIM], g_T1[CDIM];
__device__ float  g_A2[PDIM], g_T2[PDIM];
__device__ float  g_sc3[PDIM], g_sh3[PDIM];

__device__ __forceinline__ uint32_t smem_u32(const void* p) {
    uint32_t a;
    asm("{ .reg .u64 t; cvta.to.shared.u64 t, %1; cvt.u32.u64 %0, t; }" : "=r"(a) : "l"(p));
    return a;
}

// ---------------- tiny init ----------------
__global__ void zero_kernel() {
    for (int i = threadIdx.x; i < 1536; i += blockDim.x) g_red[i] = 0.f;
}

// ---------------- bn1 stats over x (NCHW): one CTA per channel ----------------
__global__ void reduce_x_kernel(const float* __restrict__ x) {
    int c = blockIdx.x;
    int tid = threadIdx.x;
    float s = 0.f, s2 = 0.f;
    const float* xc = x + (size_t)c * PIXPERIMG;
    for (int n = 0; n < NIMG; n++) {
        const float* p = xc + (size_t)n * (CDIM * PIXPERIMG);
        for (int i = tid; i < PIXPERIMG; i += 256) {
            float v = p[i];
            s += v; s2 += v * v;
        }
    }
    __shared__ float sh[256], sh2[256];
    sh[tid] = s; sh2[tid] = s2;
    __syncthreads();
    for (int o = 128; o > 0; o >>= 1) {
        if (tid < o) { sh[tid] += sh[tid + o]; sh2[tid] += sh2[tid + o]; }
        __syncthreads();
    }
    if (tid == 0) { g_red[c] = sh[0]; g_red[256 + c] = sh2[0]; }
}

// ---------------- binarize weights: sign(w - mean over input channels) ----------
__global__ void binw_kernel(const float* __restrict__ w1, const float* __restrict__ w2) {
    int p = blockIdx.x;
    int layer = blockIdx.y;
    const float* w = layer ? w2 : w1;
    int8_t* o = layer ? g_wbt2 : g_wbt1;
    int c = threadIdx.x;
    __shared__ float sh[256];
    const float* wp = w + ((size_t)p * 256 + c) * 9;
    float wv[9];
#pragma unroll
    for (int t = 0; t < 9; t++) wv[t] = wp[t];
    for (int t = 0; t < 9; t++) {
        sh[c] = wv[t];
        __syncthreads();
        for (int ofs = 128; ofs > 0; ofs >>= 1) {
            if (c < ofs) sh[c] += sh[c + ofs];
            __syncthreads();
        }
        float mean = sh[0] * (1.f / 256.f);
        __syncthreads();
        o[t * 65536 + p * 256 + c] = (wv[t] > mean) ? (int8_t)1 : (int8_t)-1;
    }
}

// ---------------- threshold coeffs for sign(bn(.)) ----------------
__global__ void make_thresh_kernel(int which, const float* __restrict__ g, const float* __restrict__ b) {
    int c = threadIdx.x;
    const float* red = which ? (g_red + 512) : g_red;
    float* A = which ? g_A2 : g_A1;
    float* T = which ? g_T2 : g_T1;
    float m = red[c] * (1.f / (float)NPIX);
    float var = red[256 + c] * (1.f / (float)NPIX) - m * m;
    A[c] = g[c];
    T[c] = b[c] * sqrtf(var + EPSV) - g[c] * m;
}

__global__ void make_bn3_kernel(const float* __restrict__ g, const float* __restrict__ b) {
    int c = threadIdx.x;
    float m = g_red[1024 + c] * (1.f / (float)NPIX);
    float var = g_red[1024 + 256 + c] * (1.f / (float)NPIX) - m * m;
    float sc = g[c] * rsqrtf(var + EPSV);
    g_sc3[c] = sc;
    g_sh3[c] = b[c] - m * sc;
}

// ---------------- binarize x: NCHW fp32 -> NHWC int8 via smem transpose ---------
__global__ void binx_kernel(const float* __restrict__ x) {
    __shared__ __align__(16) int8_t s[112 * 48];
    int tid = threadIdx.x;
    int pb = blockIdx.x * 112;
    int cb = blockIdx.y * 32;
    int n  = blockIdx.z;
#pragma unroll
    for (int i = 0; i < 14; i++) {
        int e = tid + i * 256;
        int cl = e / 112, pix = e % 112;
        int c = cb + cl;
        float v = x[((size_t)(n * CDIM + c)) * PIXPERIMG + pb + pix];
        s[pix * 48 + cl] = (g_A1[c] * v + g_T1[c] >= 0.f) ? (int8_t)1 : (int8_t)-1;
    }
    __syncthreads();
    if (tid < 224) {
        int pix = tid >> 1, half = tid & 1;
        uint4 v = *(const uint4*)&s[pix * 48 + half * 16];
        *(uint4*)(g_xb1 + (((size_t)(n * PIXPERIMG + pb + pix)) << 8) + cb + half * 16) = v;
    }
}

// ---------------- binarize y1 -> xb2 (both NHWC, fully coalesced) ----------------
__global__ void biny_kernel(const float* __restrict__ gamma1,
                            const float* __restrict__ alpha1,
                            const float* __restrict__ beta1) {
    int idx = blockIdx.x * 256 + threadIdx.x;
    int base = idx << 2;
    int pix = base >> 8;
    int c0 = base & 255;
    int r = pix % PIXPERIMG;
    float ab = alpha1[r / HWD] * beta1[r % HWD];
    short4 v = *reinterpret_cast<const short4*>(g_y1 + base);
    int cv[4] = {v.x, v.y, v.z, v.w};
    uint32_t o = 0;
#pragma unroll
    for (int j = 0; j < 4; j++) {
        int c = c0 + j;
        float val = (float)cv[j] * (gamma1[c] * ab);
        float rr = fmaxf(val, 0.f);
        int8_t sg = (g_A2[c] * rr + g_T2[c] >= 0.f) ? (int8_t)1 : (int8_t)-1;
        o |= ((uint32_t)(uint8_t)sg) << (8 * j);
    }
    *reinterpret_cast<uint32_t*>(g_xb2 + base) = o;
}

// ================== implicit-GEMM binary conv via int8 mma.sync ==================
// M=50176 px, N=256 outch, K=2304. CTA tile 128x128, K-chunk 128 B, 18 chunks.
// 2-stage cp.async ring, ONE __syncthreads per iteration, ldmatrix.x4 fragment
// loads on XOR-swizzled SMEM. Fused epilogue: int16 NHWC store + per-channel
// (sum, sumsq) of scaled (relu'd) values for the next BN's batch stats.
#define CONV_SMEM_BYTES 66560
// dyn smem layout: [0:512) pixbytes, [512:640) py, [640:768) px,
//                  [1024 : 1024+32768) A stages, [33792 : 33792+32768) B stages

__global__ void __launch_bounds__(256, 2)
conv_kernel(int layer, const float* __restrict__ gamma,
            const float* __restrict__ alpha, const float* __restrict__ beta) {
    extern __shared__ __align__(16) char dsm[];
    const int8_t* Ag = layer ? g_xb2 : g_xb1;
    const int8_t* Wg = layer ? g_wbt2 : g_wbt1;
    short* Yg = layer ? g_y2 : g_y1;
    float* red = g_red + (layer ? 1024 : 512);
    const bool doRelu = (layer == 0);

    int* pixb       = (int*)(dsm);
    signed char* py = (signed char*)(dsm + 512);
    signed char* px = (signed char*)(dsm + 640);
    uint32_t sbase = smem_u32(dsm);

    int tid = threadIdx.x;
    int mbase = blockIdx.x * 128;
    int pbase = blockIdx.y * 128;

    if (tid < 128) {
        int pix = mbase + tid;
        int r = pix % PIXPERIMG;
        pixb[tid] = pix << 8;
        py[tid] = (signed char)(r / HWD);
        px[tid] = (signed char)(r % HWD);
    }
    __syncthreads();

    // ---- staging: chunk c covers tap t=c/2, channel half h=c&1 (128 bytes) ----
    auto stage = [&](int c) {
        int t = c >> 1, h = c & 1;
        int dy = t / 3 - 1, dx = t % 3 - 1;
        int s = c & 1;
        uint32_t abase = sbase + 1024 + s * 16384;
        uint32_t bbase = sbase + 33792 + s * 16384;
        int delta = (dy * HWD + dx) * 256 + h * 128;
        const int8_t* wb = Wg + t * 65536 + h * 128;
#pragma unroll
        for (int i = 0; i < 4; i++) {
            int id = tid + i * 256;
            int row = id >> 3, seg = id & 7;
            int yy = (int)py[row] + dy, xx = (int)px[row] + dx;
            bool valid = ((unsigned)yy < (unsigned)HWD) && ((unsigned)xx < (unsigned)HWD);
            const int8_t* gp = Ag + pixb[row] + delta + seg * 16;
            uint32_t dst = abase + row * 128 + (((unsigned)(seg ^ (row & 7))) << 4);
            int sz = valid ? 16 : 0;
            asm volatile("cp.async.cg.shared.global [%0], [%1], 16, %2;\n"
                         :: "r"(dst), "l"(gp), "r"(sz));
        }
#pragma unroll
        for (int i = 0; i < 4; i++) {
            int id = tid + i * 256;
            int row = id >> 3, seg = id & 7;
            const int8_t* gp = wb + (pbase + row) * 256 + seg * 16;
            uint32_t dst = bbase + row * 128 + (((unsigned)(seg ^ (row & 7))) << 4);
            asm volatile("cp.async.cg.shared.global [%0], [%1], 16, 16;\n"
                         :: "r"(dst), "l"(gp));
        }
        asm volatile("cp.async.commit_group;\n");
    };

    int wid = tid >> 5, lane = tid & 31;
    int warpM = wid & 1, warpN = wid >> 1;     // 2 x 4 warp grid; warp tile 64x32
    int gid = lane >> 2, tig = lane & 3;

    // ldmatrix per-lane geometry
    int tl = lane >> 3;
    int arow = (lane & 7) + 8 * (tl & 1);      // A: t0/t2 rows 0-7, t1/t3 rows 8-15
    int asof = tl >> 1;                        // A: t0/t1 left 16B, t2/t3 right 16B
    int ra7 = arow & 7;
    int brow = (lane & 7) + 8 * (tl >> 1);     // B: t0/t1 rows 0-7, t2/t3 rows 8-15
    int bsof = tl & 1;                         // B: t0/t2 left, t1/t3 right
    int rb7 = brow & 7;
    uint32_t partA[4], partB[2];
#pragma unroll
    for (int mi = 0; mi < 4; mi++) partA[mi] = (uint32_t)((warpM * 64 + mi * 16 + arow) * 128);
#pragma unroll
    for (int p = 0; p < 2; p++)  partB[p]  = (uint32_t)((warpN * 32 + p * 16 + brow) * 128);

    int acc[4][4][4];
#pragma unroll
    for (int a = 0; a < 4; a++)
#pragma unroll
        for (int b = 0; b < 4; b++)
#pragma unroll
            for (int c = 0; c < 4; c++) acc[a][b][c] = 0;

    stage(0);

    for (int c = 0; c < 18; c++) {
        asm volatile("cp.async.wait_group 0;\n" ::: "memory");
        __syncthreads();
        if (c < 17) stage(c + 1);

        uint32_t Ab = sbase + 1024 + (c & 1) * 16384;
        uint32_t Bb = sbase + 33792 + (c & 1) * 16384;
#pragma unroll
        for (int h = 0; h < 4; h++) {
            uint32_t af[4][4];
#pragma unroll
            for (int mi = 0; mi < 4; mi++) {
                uint32_t ad = Ab + partA[mi] + ((uint32_t)(((2 * h + asof) ^ ra7)) << 4);
                asm volatile("ldmatrix.sync.aligned.m8n8.x4.shared.b16 {%0,%1,%2,%3}, [%4];"
                             : "=r"(af[mi][0]), "=r"(af[mi][1]), "=r"(af[mi][2]), "=r"(af[mi][3])
                             : "r"(ad));
            }
            uint32_t bf[4][2];
#pragma unroll
            for (int p = 0; p < 2; p++) {
                uint32_t bd = Bb + partB[p] + ((uint32_t)(((2 * h + bsof) ^ rb7)) << 4);
                asm volatile("ldmatrix.sync.aligned.m8n8.x4.shared.b16 {%0,%1,%2,%3}, [%4];"
                             : "=r"(bf[2 * p][0]), "=r"(bf[2 * p][1]),
                               "=r"(bf[2 * p + 1][0]), "=r"(bf[2 * p + 1][1])
                             : "r"(bd));
            }
#pragma unroll
            for (int mi = 0; mi < 4; mi++)
#pragma unroll
                for (int ni = 0; ni < 4; ni++) {
                    asm volatile(
                        "mma.sync.aligned.m16n8k32.row.col.s32.s8.s8.s32 "
                        "{%0,%1,%2,%3}, {%4,%5,%6,%7}, {%8,%9}, {%0,%1,%2,%3};\n"
                        : "+r"(acc[mi][ni][0]), "+r"(acc[mi][ni][1]),
                          "+r"(acc[mi][ni][2]), "+r"(acc[mi][ni][3])
                        : "r"(af[mi][0]), "r"(af[mi][1]), "r"(af[mi][2]), "r"(af[mi][3]),
                          "r"(bf[ni][0]), "r"(bf[ni][1]));
                }
        }
    }

    // ---- epilogue: int16 store + fused per-channel stats of scaled values ----
    float gm[4][2];
#pragma unroll
    for (int ni = 0; ni < 4; ni++) {
        gm[ni][0] = gamma[pbase + warpN * 32 + ni * 8 + tig * 2 + 0];
        gm[ni][1] = gamma[pbase + warpN * 32 + ni * 8 + tig * 2 + 1];
    }
    float sv[4][2], sq[4][2];
#pragma unroll
    for (int ni = 0; ni < 4; ni++) { sv[ni][0] = sv[ni][1] = sq[ni][0] = sq[ni][1] = 0.f; }

#pragma unroll
    for (int mi = 0; mi < 4; mi++) {
#pragma unroll
        for (int rh = 0; rh < 2; rh++) {
            int prow = warpM * 64 + mi * 16 + rh * 8 + gid;
            int pix = mbase + prow;
            float ab = alpha[(int)py[prow]] * beta[(int)px[prow]];
#pragma unroll
            for (int ni = 0; ni < 4; ni++) {
                int i0 = acc[mi][ni][rh * 2 + 0];
                int i1 = acc[mi][ni][rh * 2 + 1];
                float v0 = (float)i0 * (gm[ni][0] * ab);
                float v1 = (float)i1 * (gm[ni][1] * ab);
                if (doRelu) { v0 = fmaxf(v0, 0.f); v1 = fmaxf(v1, 0.f); }
                sv[ni][0] += v0; sq[ni][0] += v0 * v0;
                sv[ni][1] += v1; sq[ni][1] += v1 * v1;
                uint32_t packed = (uint32_t)(uint16_t)(short)i0 |
                                  ((uint32_t)(uint16_t)(short)i1 << 16);
                *(uint32_t*)(Yg + (size_t)pix * 256 + pbase + warpN * 32 + ni * 8 + tig * 2) = packed;
            }
        }
    }
#pragma unroll
    for (int ofs = 4; ofs <= 16; ofs <<= 1) {
#pragma unroll
        for (int ni = 0; ni < 4; ni++) {
#pragma unroll
            for (int c = 0; c < 2; c++) {
                sv[ni][c] += __shfl_xor_sync(0xffffffff, sv[ni][c], ofs);
                sq[ni][c] += __shfl_xor_sync(0xffffffff, sq[ni][c], ofs);
            }
        }
    }
    if (gid == 0) {
#pragma unroll
        for (int ni = 0; ni < 4; ni++) {
#pragma unroll
            for (int c = 0; c < 2; c++) {
                int p = pbase + warpN * 32 + ni * 8 + tig * 2 + c;
                atomicAdd(&red[p], sv[ni][c]);
                atomicAdd(&red[256 + p], sq[ni][c]);
            }
        }
    }
}

// ---------------- final: out = relu(bn3(y2*s2) + x), NHWC int16 -> NCHW fp32 ----
__global__ void final_kernel(const float* __restrict__ x,
                             const float* __restrict__ gamma2,
                             const float* __restrict__ alpha2,
                             const float* __restrict__ beta2,
                             float* __restrict__ out) {
    __shared__ float fs[32 * 113];
    int tid = threadIdx.x;
    int pb = blockIdx.x * 112;
    int cb = blockIdx.y * 32;
    int n  = blockIdx.z;
#pragma unroll
    for (int i = 0; i < 14; i++) {
        int e = tid + i * 256;
        int pix = e >> 5, cl = e & 31;
        int c = cb + cl;
        int pg = pb + pix;
        int cint = g_y2[(((size_t)(n * PIXPERIMG + pg)) << 8) + c];
        float v = (float)cint * (gamma2[c] * alpha2[pg / HWD] * beta2[pg % HWD]);
        fs[cl * 113 + pix] = v * g_sc3[c] + g_sh3[c];
    }
    __syncthreads();
#pragma unroll
    for (int i = 0; i < 14; i++) {
        int e = tid + i * 256;
        int cl = e / 112, pix = e % 112;
        int c = cb + cl;
        size_t gi = ((size_t)(n * CDIM + c)) * PIXPERIMG + pb + pix;
        out[gi] = fmaxf(fs[cl * 113 + pix] + x[gi], 0.f);
    }
}

// ---------------- launch ----------------
extern "C" void kernel_launch(void* const* d_in, const int* in_sizes, int n_in,
                              void* d_out, int out_size) {
    (void)in_sizes; (void)n_in; (void)out_size;
    const float* x      = (const float*)d_in[0];
    const float* bn1_g  = (const float*)d_in[1];
    const float* bn1_b  = (const float*)d_in[2];
    const float* bn2_g  = (const float*)d_in[3];
    const float* bn2_b  = (const float*)d_in[4];
    const float* bn3_g  = (const float*)d_in[5];
    const float* bn3_b  = (const float*)d_in[6];
    const float* w1     = (const float*)d_in[7];
    const float* gamma1 = (const float*)d_in[8];
    const float* alpha1 = (const float*)d_in[9];
    const float* beta1  = (const float*)d_in[10];
    const float* w2     = (const float*)d_in[11];
    const float* gamma2 = (const float*)d_in[12];
    const float* alpha2 = (const float*)d_in[13];
    const float* beta2  = (const float*)d_in[14];
    float* out = (float*)d_out;

    cudaFuncSetAttribute(conv_kernel,
                         cudaFuncAttributeMaxDynamicSharedMemorySize, CONV_SMEM_BYTES);

    zero_kernel<<<1, 512>>>();
    reduce_x_kernel<<<256, 256>>>(x);
    binw_kernel<<<dim3(256, 2), 256>>>(w1, w2);
    make_thresh_kernel<<<1, 256>>>(0, bn1_g, bn1_b);
    binx_kernel<<<dim3(7, 8, 64), 256>>>(x);
    conv_kernel<<<dim3(392, 2), 256, CONV_SMEM_BYTES>>>(0, gamma1, alpha1, beta1);
    make_thresh_kernel<<<1, 256>>>(1, bn2_g, bn2_b);
    biny_kernel<<<12544, 256>>>(gamma1, alpha1, beta1);
    conv_kernel<<<dim3(392, 2), 256, CONV_SMEM_BYTES>>>(1, gamma2, alpha2, beta2);
    make_bn3_kernel<<<1, 256>>>(bn3_g, bn3_b);
    final_kernel<<<dim3(7, 8, 64), 256>>>(x, gamma2, alpha2, beta2, out);
}

// round 7
// speedup vs baseline: 1.2000x; 1.0123x over previous
#include <cuda_runtime.h>
#include <cstdint>

#define NIMG 64
#define CDIM 256
#define HWD 28
#define PIXPERIMG 784
#define NPIX 50176   /* 64*784 */
#define PDIM 256
#define EPSV 1e-5f

// Padded geometry: image n, row y lives at padded row R = n*29 + y + 1.
// Row R = multiple of 29 => zero separator (shared bottom/top border).
// Column x lives at cx = x+1; cx=0,29 are zero borders. Padded pos = R*30+cx.
#define NPADROWS 1857          /* 64*29+1 */
#define NPADPOS  55710         /* 1857*30 */

// ---------------- scratch (device globals; no allocation allowed) ----------------
__device__ __align__(256) int8_t g_xp1[NPADPOS * 256];   // padded+swizzled sign(bn1(x))
__device__ __align__(256) int8_t g_xp2[NPADPOS * 256];   // padded+swizzled sign(bn2(relu))
__device__ __align__(256) int8_t g_wbt1[9 * 2 * 256 * 128]; // [tap][half][p][sw 128B]
__device__ __align__(256) int8_t g_wbt2[9 * 2 * 256 * 128];
__device__ short  g_y1[NPIX * PDIM];           // raw conv1 int result NHWC (unpadded)
__device__ short  g_y2[NPIX * PDIM];
__device__ float  g_red[1536];
__device__ float  g_A1[CDIM], g_T1[CDIM];
__device__ float  g_A2[PDIM], g_T2[PDIM];
__device__ float  g_sc3[PDIM], g_sh3[PDIM];

__device__ __forceinline__ uint32_t smem_u32(const void* p) {
    uint32_t a;
    asm("{ .reg .u64 t; cvta.to.shared.u64 t, %1; cvt.u32.u64 %0, t; }" : "=r"(a) : "l"(p));
    return a;
}
__device__ __forceinline__ void mbar_init(uint32_t a, uint32_t cnt) {
    asm volatile("mbarrier.init.shared.b64 [%0], %1;" :: "r"(a), "r"(cnt) : "memory");
}
__device__ __forceinline__ void mbar_wait(uint32_t a, uint32_t par) {
    uint32_t done;
    asm volatile("{\n\t.reg .pred p;\n\t"
                 "mbarrier.try_wait.parity.acquire.cta.shared::cta.b64 p, [%1], %2;\n\t"
                 "selp.b32 %0,1,0,p;\n\t}"
                 : "=r"(done) : "r"(a), "r"(par) : "memory");
    while (!done) {
        asm volatile("{\n\t.reg .pred p;\n\t"
                     "mbarrier.try_wait.parity.acquire.cta.shared::cta.b64 p, [%1], %2, 0x989680;\n\t"
                     "selp.b32 %0,1,0,p;\n\t}"
                     : "=r"(done) : "r"(a), "r"(par) : "memory");
    }
}
__device__ __forceinline__ void bulk_g2s(uint32_t dst, const void* src, uint32_t bytes, uint32_t mbar) {
    asm volatile("mbarrier.arrive.expect_tx.shared.b64 _, [%0], %1;" :: "r"(mbar), "r"(bytes) : "memory");
    asm volatile("cp.async.bulk.shared::cluster.global.mbarrier::complete_tx::bytes [%0], [%1], %2, [%3];"
                 :: "r"(dst), "l"(src), "r"(bytes), "r"(mbar) : "memory");
}

// ---------------- tiny init ----------------
__global__ void zero_kernel() {
    for (int i = threadIdx.x; i < 1536; i += blockDim.x) g_red[i] = 0.f;
}

// zero the border rows/cols of both padded activation buffers
__global__ void pad_zero_kernel() {
    int idx = blockIdx.x * 256 + threadIdx.x;
    if (idx >= NPADPOS) return;
    int R = idx / 30, cx = idx % 30;
    if ((R % 29) == 0 || cx == 0 || cx == 29) {
        uint4 z = make_uint4(0, 0, 0, 0);
        uint4* a = (uint4*)(g_xp1 + (size_t)idx * 256);
        uint4* b = (uint4*)(g_xp2 + (size_t)idx * 256);
#pragma unroll
        for (int i = 0; i < 16; i++) { a[i] = z; b[i] = z; }
    }
}

// ---------------- bn1 stats over x (NCHW): one CTA per channel ----------------
__global__ void reduce_x_kernel(const float* __restrict__ x) {
    int c = blockIdx.x;
    int tid = threadIdx.x;
    float s = 0.f, s2 = 0.f;
    const float* xc = x + (size_t)c * PIXPERIMG;
    for (int n = 0; n < NIMG; n++) {
        const float* p = xc + (size_t)n * (CDIM * PIXPERIMG);
        for (int i = tid; i < PIXPERIMG; i += 256) {
            float v = p[i];
            s += v; s2 += v * v;
        }
    }
    __shared__ float sh[256], sh2[256];
    sh[tid] = s; sh2[tid] = s2;
    __syncthreads();
    for (int o = 128; o > 0; o >>= 1) {
        if (tid < o) { sh[tid] += sh[tid + o]; sh2[tid] += sh2[tid + o]; }
        __syncthreads();
    }
    if (tid == 0) { g_red[c] = sh[0]; g_red[256 + c] = sh2[0]; }
}

// ---------------- binarize weights -> [tap][half][p][sw128] ----------
__global__ void binw_kernel(const float* __restrict__ w1, const float* __restrict__ w2) {
    int p = blockIdx.x;
    int layer = blockIdx.y;
    const float* w = layer ? w2 : w1;
    int8_t* o = layer ? g_wbt2 : g_wbt1;
    int c = threadIdx.x;
    __shared__ float sh[256];
    const float* wp = w + ((size_t)p * 256 + c) * 9;
    float wv[9];
#pragma unroll
    for (int t = 0; t < 9; t++) wv[t] = wp[t];
    int half = c >> 7, seg = (c >> 4) & 7, inner = c & 15;
    int off0 = half * 32768 + p * 128 + ((seg ^ (p & 7)) << 4) + inner;
    for (int t = 0; t < 9; t++) {
        sh[c] = wv[t];
        __syncthreads();
        for (int ofs = 128; ofs > 0; ofs >>= 1) {
            if (c < ofs) sh[c] += sh[c + ofs];
            __syncthreads();
        }
        float mean = sh[0] * (1.f / 256.f);
        __syncthreads();
        o[t * 65536 + off0] = (wv[t] > mean) ? (int8_t)1 : (int8_t)-1;
    }
}

// ---------------- threshold coeffs for sign(bn(.)) ----------------
__global__ void make_thresh_kernel(int which, const float* __restrict__ g, const float* __restrict__ b) {
    int c = threadIdx.x;
    const float* red = which ? (g_red + 512) : g_red;
    float* A = which ? g_A2 : g_A1;
    float* T = which ? g_T2 : g_T1;
    float m = red[c] * (1.f / (float)NPIX);
    float var = red[256 + c] * (1.f / (float)NPIX) - m * m;
    A[c] = g[c];
    T[c] = b[c] * sqrtf(var + EPSV) - g[c] * m;
}

__global__ void make_bn3_kernel(const float* __restrict__ g, const float* __restrict__ b) {
    int c = threadIdx.x;
    float m = g_red[1024 + c] * (1.f / (float)NPIX);
    float var = g_red[1024 + 256 + c] * (1.f / (float)NPIX) - m * m;
    float sc = g[c] * rsqrtf(var + EPSV);
    g_sc3[c] = sc;
    g_sh3[c] = b[c] - m * sc;
}

// ---------------- binarize x: NCHW fp32 -> padded swizzled int8 ----------------
__global__ void binx_kernel(const float* __restrict__ x) {
    __shared__ __align__(16) int8_t s[112 * 48];
    int tid = threadIdx.x;
    int pb = blockIdx.x * 112;
    int cb = blockIdx.y * 32;
    int n  = blockIdx.z;
#pragma unroll
    for (int i = 0; i < 14; i++) {
        int e = tid + i * 256;
        int cl = e / 112, pix = e % 112;
        int c = cb + cl;
        float v = x[((size_t)(n * CDIM + c)) * PIXPERIMG + pb + pix];
        s[pix * 48 + cl] = (g_A1[c] * v + g_T1[c] >= 0.f) ? (int8_t)1 : (int8_t)-1;
    }
    __syncthreads();
    if (tid < 224) {
        int pix = tid >> 1, half = tid & 1;
        int pg = pb + pix;
        int y = pg / HWD, xx = pg % HWD;
        int P = (n * 29 + y + 1) * 30 + xx + 1;
        int seg = (cb >> 4) + half;              // 0..15
        uint4 v = *(const uint4*)&s[pix * 48 + half * 16];
        *(uint4*)(g_xp1 + (size_t)P * 256 + ((seg ^ (P & 7)) << 4)) = v;
    }
}

// ---------------- binarize y1 -> xp2 (padded swizzled) ----------------
__global__ void biny_kernel(const float* __restrict__ gamma1,
                            const float* __restrict__ alpha1,
                            const float* __restrict__ beta1) {
    int idx = blockIdx.x * 256 + threadIdx.x;
    int base = idx << 2;
    int pix = base >> 8;
    int c0 = base & 255;
    int n = pix / PIXPERIMG, pg = pix % PIXPERIMG;
    int y = pg / HWD, xx = pg % HWD;
    float ab = alpha1[y] * beta1[xx];
    short4 v = *reinterpret_cast<const short4*>(g_y1 + base);
    int cv[4] = {v.x, v.y, v.z, v.w};
    uint32_t o = 0;
#pragma unroll
    for (int j = 0; j < 4; j++) {
        int c = c0 + j;
        float val = (float)cv[j] * (gamma1[c] * ab);
        float rr = fmaxf(val, 0.f);
        int8_t sg = (g_A2[c] * rr + g_T2[c] >= 0.f) ? (int8_t)1 : (int8_t)-1;
        o |= ((uint32_t)(uint8_t)sg) << (8 * j);
    }
    int P = (n * 29 + y + 1) * 30 + xx + 1;
    int seg = c0 >> 4, inner = c0 & 15;
    *reinterpret_cast<uint32_t*>(g_xp2 + (size_t)P * 256 + ((seg ^ (P & 7)) << 4) + inner) = o;
}

// ================== implicit-GEMM binary conv, bulk-copy fed ==================
// CTA tile 128 px x 128 outch. A halo (<=240 padded rows x 256B) loaded ONCE by
// one cp.async.bulk; B chunks (16KB contiguous, pre-swizzled) double-buffered
// via cp.async.bulk + mbarrier. Mainloop = pure ldmatrix + mma.
#define HALO_BYTES 61440
#define CONV_SMEM_BYTES (1024 + HALO_BYTES + 2 * 16384)

__global__ void __launch_bounds__(256, 2)
conv_kernel(int layer, const float* __restrict__ gamma,
            const float* __restrict__ alpha, const float* __restrict__ beta) {
    extern __shared__ __align__(128) char dsm[];
    const int8_t* Ag = layer ? g_xp2 : g_xp1;
    const int8_t* Wg = layer ? g_wbt2 : g_wbt1;
    short* Yg = layer ? g_y2 : g_y1;
    float* red = g_red + (layer ? 1024 : 512);
    const bool doRelu = (layer == 0);

    uint32_t sbase = smem_u32(dsm);
    uint32_t mb = sbase;                          // mbar: halo @0, B0 @8, B1 @16
    int*  prow = (int*)(dsm + 64);                // padded pos per output row
    signed char* py = (signed char*)(dsm + 576);
    signed char* px = (signed char*)(dsm + 704);
    uint32_t haloS = sbase + 1024;
    uint32_t bS    = sbase + 1024 + HALO_BYTES;

    int tid = threadIdx.x;
    int mbase = blockIdx.x * 128;
    int pbase = blockIdx.y * 128;

    if (tid < 128) {
        int pix = mbase + tid;
        int n = pix / PIXPERIMG, pg = pix % PIXPERIMG;
        int y = pg / HWD, x = pg % HWD;
        prow[tid] = (n * 29 + y + 1) * 30 + x + 1;
        py[tid] = (signed char)y; px[tid] = (signed char)x;
    }
    if (tid == 0) { mbar_init(mb, 1); mbar_init(mb + 8, 1); mbar_init(mb + 16, 1); }
    __syncthreads();

    int P0 = prow[0], P127 = prow[127];
    int G0 = (P0 - 31) & ~7;
    if (tid == 0) {
        uint32_t hbytes = (uint32_t)(P127 + 31 - G0 + 1) * 256;
        bulk_g2s(haloS, Ag + (size_t)G0 * 256, hbytes, mb);
        bulk_g2s(bS,         Wg + 0 * 32768 + pbase * 128, 16384u, mb + 8);
        bulk_g2s(bS + 16384, Wg + 1 * 32768 + pbase * 128, 16384u, mb + 16);
    }

    int wid = tid >> 5, lane = tid & 31;
    int warpM = wid & 1, warpN = wid >> 1;        // 2 x 4 warps; warp tile 64x32
    int gid = lane >> 2, tig = lane & 3;

    int tl = lane >> 3;
    int arow = (lane & 7) + 8 * (tl & 1);
    int asof = tl >> 1;
    int brow = (lane & 7) + 8 * (tl >> 1);
    int bsof = tl & 1;
    int rb7 = brow & 7;

    int prowR[4];
#pragma unroll
    for (int mi = 0; mi < 4; mi++)
        prowR[mi] = prow[warpM * 64 + mi * 16 + arow] - G0;
    uint32_t partB[2];
#pragma unroll
    for (int p = 0; p < 2; p++) partB[p] = (uint32_t)((warpN * 32 + p * 16 + brow) * 128);

    int acc[4][4][4];
#pragma unroll
    for (int a = 0; a < 4; a++)
#pragma unroll
        for (int b = 0; b < 4; b++)
#pragma unroll
            for (int c = 0; c < 4; c++) acc[a][b][c] = 0;

    mbar_wait(mb, 0);                              // halo resident

    for (int c = 0; c < 18; c++) {
        mbar_wait(mb + 8 + 8 * (c & 1), (c >> 1) & 1);
        int t = c >> 1, hc = c & 1;
        int tapoff = (t / 3 - 1) * 30 + (t % 3 - 1);
        uint32_t Bb = bS + 16384u * (c & 1);
        uint32_t abase[4]; int a7[4];
#pragma unroll
        for (int mi = 0; mi < 4; mi++) {
            int rl = prowR[mi] + tapoff;
            abase[mi] = haloS + (uint32_t)(rl << 8) + (uint32_t)(hc << 7);
            a7[mi] = rl & 7;
        }
#pragma unroll
        for (int h = 0; h < 4; h++) {
            uint32_t af[4][4];
#pragma unroll
            for (int mi = 0; mi < 4; mi++) {
                uint32_t ad = abase[mi] + ((uint32_t)((2 * h + asof) ^ a7[mi]) << 4);
                asm volatile("ldmatrix.sync.aligned.m8n8.x4.shared.b16 {%0,%1,%2,%3}, [%4];"
                             : "=r"(af[mi][0]), "=r"(af[mi][1]), "=r"(af[mi][2]), "=r"(af[mi][3])
                             : "r"(ad));
            }
            uint32_t bf[4][2];
#pragma unroll
            for (int p = 0; p < 2; p++) {
                uint32_t bd = Bb + partB[p] + ((uint32_t)(((2 * h + bsof) ^ rb7)) << 4);
                asm volatile("ldmatrix.sync.aligned.m8n8.x4.shared.b16 {%0,%1,%2,%3}, [%4];"
                             : "=r"(bf[2 * p][0]), "=r"(bf[2 * p][1]),
                               "=r"(bf[2 * p + 1][0]), "=r"(bf[2 * p + 1][1])
                             : "r"(bd));
            }
#pragma unroll
            for (int mi = 0; mi < 4; mi++)
#pragma unroll
                for (int ni = 0; ni < 4; ni++) {
                    asm volatile(
                        "mma.sync.aligned.m16n8k32.row.col.s32.s8.s8.s32 "
                        "{%0,%1,%2,%3}, {%4,%5,%6,%7}, {%8,%9}, {%0,%1,%2,%3};\n"
                        : "+r"(acc[mi][ni][0]), "+r"(acc[mi][ni][1]),
                          "+r"(acc[mi][ni][2]), "+r"(acc[mi][ni][3])
                        : "r"(af[mi][0]), "r"(af[mi][1]), "r"(af[mi][2]), "r"(af[mi][3]),
                          "r"(bf[ni][0]), "r"(bf[ni][1]));
                }
        }
        __syncthreads();                           // readers done before refill
        if (tid == 0 && c + 2 < 18) {
            int c2 = c + 2;
            bulk_g2s(bS + 16384u * (c & 1),
                     Wg + (c2 >> 1) * 65536 + (c2 & 1) * 32768 + pbase * 128,
                     16384u, mb + 8 + 8 * (c & 1));
        }
    }

    // ---- epilogue: int16 store + fused per-channel stats of scaled values ----
    float gm[4][2];
#pragma unroll
    for (int ni = 0; ni < 4; ni++) {
        gm[ni][0] = gamma[pbase + warpN * 32 + ni * 8 + tig * 2 + 0];
        gm[ni][1] = gamma[pbase + warpN * 32 + ni * 8 + tig * 2 + 1];
    }
    float sv[4][2], sq[4][2];
#pragma unroll
    for (int ni = 0; ni < 4; ni++) { sv[ni][0] = sv[ni][1] = sq[ni][0] = sq[ni][1] = 0.f; }

#pragma unroll
    for (int mi = 0; mi < 4; mi++) {
#pragma unroll
        for (int rh = 0; rh < 2; rh++) {
            int prw = warpM * 64 + mi * 16 + rh * 8 + gid;
            int pix = mbase + prw;
            float ab = alpha[(int)py[prw]] * beta[(int)px[prw]];
#pragma unroll
            for (int ni = 0; ni < 4; ni++) {
                int i0 = acc[mi][ni][rh * 2 + 0];
                int i1 = acc[mi][ni][rh * 2 + 1];
                float v0 = (float)i0 * (gm[ni][0] * ab);
                float v1 = (float)i1 * (gm[ni][1] * ab);
                if (doRelu) { v0 = fmaxf(v0, 0.f); v1 = fmaxf(v1, 0.f); }
                sv[ni][0] += v0; sq[ni][0] += v0 * v0;
                sv[ni][1] += v1; sq[ni][1] += v1 * v1;
                uint32_t packed = (uint32_t)(uint16_t)(short)i0 |
                                  ((uint32_t)(uint16_t)(short)i1 << 16);
                *(uint32_t*)(Yg + (size_t)pix * 256 + pbase + warpN * 32 + ni * 8 + tig * 2) = packed;
            }
        }
    }
#pragma unroll
    for (int ofs = 4; ofs <= 16; ofs <<= 1) {
#pragma unroll
        for (int ni = 0; ni < 4; ni++) {
#pragma unroll
            for (int c = 0; c < 2; c++) {
                sv[ni][c] += __shfl_xor_sync(0xffffffff, sv[ni][c], ofs);
                sq[ni][c] += __shfl_xor_sync(0xffffffff, sq[ni][c], ofs);
            }
        }
    }
    if (gid == 0) {
#pragma unroll
        for (int ni = 0; ni < 4; ni++) {
#pragma unroll
            for (int c = 0; c < 2; c++) {
                int p = pbase + warpN * 32 + ni * 8 + tig * 2 + c;
                atomicAdd(&red[p], sv[ni][c]);
                atomicAdd(&red[256 + p], sq[ni][c]);
            }
        }
    }
}

// ---------------- final: out = relu(bn3(y2*s2) + x), NHWC int16 -> NCHW fp32 ----
__global__ void final_kernel(const float* __restrict__ x,
                             const float* __restrict__ gamma2,
                             const float* __restrict__ alpha2,
                             const float* __restrict__ beta2,
                             float* __restrict__ out) {
    __shared__ float fs[32 * 113];
    int tid = threadIdx.x;
    int pb = blockIdx.x * 112;
    int cb = blockIdx.y * 32;
    int n  = blockIdx.z;
#pragma unroll
    for (int i = 0; i < 14; i++) {
        int e = tid + i * 256;
        int pix = e >> 5, cl = e & 31;
        int c = cb + cl;
        int pg = pb + pix;
        int cint = g_y2[(((size_t)(n * PIXPERIMG + pg)) << 8) + c];
        float v = (float)cint * (gamma2[c] * alpha2[pg / HWD] * beta2[pg % HWD]);
        fs[cl * 113 + pix] = v * g_sc3[c] + g_sh3[c];
    }
    __syncthreads();
#pragma unroll
    for (int i = 0; i < 14; i++) {
        int e = tid + i * 256;
        int cl = e / 112, pix = e % 112;
        int c = cb + cl;
        size_t gi = ((size_t)(n * CDIM + c)) * PIXPERIMG + pb + pix;
        out[gi] = fmaxf(fs[cl * 113 + pix] + x[gi], 0.f);
    }
}

// ---------------- launch ----------------
extern "C" void kernel_launch(void* const* d_in, const int* in_sizes, int n_in,
                              void* d_out, int out_size) {
    (void)in_sizes; (void)n_in; (void)out_size;
    const float* x      = (const float*)d_in[0];
    const float* bn1_g  = (const float*)d_in[1];
    const float* bn1_b  = (const float*)d_in[2];
    const float* bn2_g  = (const float*)d_in[3];
    const float* bn2_b  = (const float*)d_in[4];
    const float* bn3_g  = (const float*)d_in[5];
    const float* bn3_b  = (const float*)d_in[6];
    const float* w1     = (const float*)d_in[7];
    const float* gamma1 = (const float*)d_in[8];
    const float* alpha1 = (const float*)d_in[9];
    const float* beta1  = (const float*)d_in[10];
    const float* w2     = (const float*)d_in[11];
    const float* gamma2 = (const float*)d_in[12];
    const float* alpha2 = (const float*)d_in[13];
    const float* beta2  = (const float*)d_in[14];
    float* out = (float*)d_out;

    cudaFuncSetAttribute(conv_kernel,
                         cudaFuncAttributeMaxDynamicSharedMemorySize, CONV_SMEM_BYTES);

    zero_kernel<<<1, 512>>>();
    pad_zero_kernel<<<(NPADPOS + 255) / 256, 256>>>();
    reduce_x_kernel<<<256, 256>>>(x);
    binw_kernel<<<dim3(256, 2), 256>>>(w1, w2);
    make_thresh_kernel<<<1, 256>>>(0, bn1_g, bn1_b);
    binx_kernel<<<dim3(7, 8, 64), 256>>>(x);
    conv_kernel<<<dim3(392, 2), 256, CONV_SMEM_BYTES>>>(0, gamma1, alpha1, beta1);
    make_thresh_kernel<<<1, 256>>>(1, bn2_g, bn2_b);
    biny_kernel<<<12544, 256>>>(gamma1, alpha1, beta1);
    conv_kernel<<<dim3(392, 2), 256, CONV_SMEM_BYTES>>>(1, gamma2, alpha2, beta2);
    make_bn3_kernel<<<1, 256>>>(bn3_g, bn3_b);
    final_kernel<<<dim3(7, 8, 64), 256>>>(x, gamma2, alpha2, beta2, out);
}